// round 12
// baseline (speedup 1.0000x reference)
#include <cuda_runtime.h>
#include <cstdint>

// Problem constants (fixed shapes in reference_code)
#define BB     1024
#define CC     20
#define NN     26
#define VDIM   128
#define NSPL   10
#define NWORDS 100000

// Scratch for x[b,v] lives in the TAIL of d_out (start of the D region),
// which the final memcpy overwrites with D afterwards on the same stream.
// -> no __device__ globals, no allocations, fully deterministic.

// K1: x[b,v] = (1/C) * sum_c ( D[knot[b], ctx[b,c], v] * x_vals[b] + W[ctx[b,c], v] )
// One block per b, 128 threads (v = tid). Writes x to scratch.
__global__ void __launch_bounds__(128)
dmspline_phase1(const float* __restrict__ x_vals,
                const int*   __restrict__ knot_ids,
                const int*   __restrict__ context_ids,
                const float* __restrict__ D,
                const float* __restrict__ W,
                float* __restrict__ xscratch)
{
    __shared__ int sctx[CC];
    const int bid = blockIdx.x;
    const int tid = threadIdx.x;

    if (tid < CC) sctx[tid] = context_ids[bid * CC + tid];
    __syncthreads();

    const int   knot = knot_ids[bid];
    const float xv   = x_vals[bid];
    const float* __restrict__ Dk = D + (size_t)knot * NWORDS * VDIM;

    float acc = 0.0f;
    #pragma unroll
    for (int c = 0; c < CC; ++c) {
        const int ctx = sctx[c];
        const float d = __ldg(Dk + (size_t)ctx * VDIM + tid);
        const float w = __ldg(W  + (size_t)ctx * VDIM + tid);
        acc = fmaf(d, xv, acc) + w;
    }
    xscratch[bid * VDIM + tid] = acc * (1.0f / CC);
}

// K2: scores[b,n] = sum_v x[b,v] * O[v, tgt[b,n]]
// ONE WARP PER OUTPUT: 26624 warps (3328 blocks x 8 warps). Each thread does
// 4 scattered O loads with a tiny register footprint, so tens of thousands
// of concurrent warps keep the DRAM sector queues full.
__global__ void __launch_bounds__(256)
dmspline_phase2(const int*   __restrict__ target_ids,
                const float* __restrict__ O,
                const float* __restrict__ xscratch,
                float* __restrict__ out)
{
    const int gw   = blockIdx.x * 8 + (threadIdx.x >> 5);  // global warp id
    const int lane = threadIdx.x & 31;
    if (gw >= BB * NN) return;

    const int b = gw / NN;
    const int n = gw - b * NN;

    const int id = __ldg(target_ids + b * NN + n);         // broadcast load
    const float* __restrict__ Ocol = O + id;
    const float* __restrict__ xrow = xscratch + b * VDIM;

    // Front-load all 4 gathers + 4 coalesced x loads (8 loads in flight).
    float o0 = __ldg(Ocol + (size_t)(lane      ) * NWORDS);
    float o1 = __ldg(Ocol + (size_t)(lane + 32 ) * NWORDS);
    float o2 = __ldg(Ocol + (size_t)(lane + 64 ) * NWORDS);
    float o3 = __ldg(Ocol + (size_t)(lane + 96 ) * NWORDS);
    float x0 = __ldg(xrow + lane);
    float x1 = __ldg(xrow + lane + 32);
    float x2 = __ldg(xrow + lane + 64);
    float x3 = __ldg(xrow + lane + 96);

    float s = 0.0f;
    s = fmaf(x0, o0, s);
    s = fmaf(x1, o1, s);
    s = fmaf(x2, o2, s);
    s = fmaf(x3, o3, s);

    #pragma unroll
    for (int off = 16; off; off >>= 1)
        s += __shfl_down_sync(0xffffffffu, s, off);
    if (lane == 0) out[b * NN + n] = s;
}

extern "C" void kernel_launch(void* const* d_in, const int* in_sizes, int n_in,
                              void* d_out, int out_size)
{
    const float* x_vals      = (const float*)d_in[0];
    const int*   knot_ids    = (const int*)  d_in[1];
    const int*   context_ids = (const int*)  d_in[2];
    const int*   target_ids  = (const int*)  d_in[3];
    const float* D           = (const float*)d_in[4];
    const float* W           = (const float*)d_in[5];
    const float* O           = (const float*)d_in[6];
    float*       out         = (float*)d_out;

    const long long dElems = (long long)NSPL * NWORDS * VDIM;   // 128,000,000
    const long long need   = (long long)BB * NN + dElems;
    const bool full_out = ((long long)out_size >= need);

    // Scratch region: start of the D-output area (overwritten by the memcpy
    // below AFTER phase2 has consumed it — same-stream ordering guarantees).
    // BB*VDIM = 131072 floats << dElems, so it fits.
    float* xscratch = out + (size_t)BB * NN;

    // Phase 1: x into scratch (~3 us)
    dmspline_phase1<<<BB, 128>>>(x_vals, knot_ids, context_ids, D, W, xscratch);

    // Phase 2: one warp per (b,n); 26624 warps (~10 us)
    dmspline_phase2<<<(BB * NN + 7) / 8, 256>>>(target_ids, O, xscratch, out);

    // D pass-through via the driver's D2D memcpy (proven ~7.2 TB/s; proven
    // non-overlappable with kernels). Overwrites the scratch region with the
    // correct D contents.
    if (full_out) {
        cudaMemcpyAsync(out + (size_t)BB * NN, D,
                        (size_t)dElems * sizeof(float),
                        cudaMemcpyDeviceToDevice, 0);
    }
}